// round 1
// baseline (speedup 1.0000x reference)
#include <cuda_runtime.h>
#include <cuda_bf16.h>

// ---------------------------------------------------------------------------
// DynamicModel hypernetwork:
//   MLP(16->256->512->19296, relu all layers) generates per-sample conv weights
//   conv0: 1->32, 3x3 SAME ; conv1: 32->64 ; conv2: 64->1   (per batch sample)
//   B=16, H=W=256
// ---------------------------------------------------------------------------

#define ULL unsigned long long

static const int B = 16, H = 256, W = 256;
static const int TOTAL_W = 19296;      // 288 + 18432 + 576
static const int OFF_W1 = 288;         // conv1 weights offset in flat
static const int OFF_W2 = 18720;       // conv2 weights offset

// Scratch (device globals: allocation-free)
__device__ float g_h1[16 * 512];
__device__ float g_flat[16 * TOTAL_W];
__device__ float g_c0[16 * 32 * 256 * 256];   // 128 MB
__device__ float g_c1[(size_t)16 * 64 * 256 * 256];   // 256 MB

// ---------------- packed fp32x2 helpers ----------------
__device__ __forceinline__ ULL pack2(float v) {
    ULL r; unsigned u = __float_as_uint(v);
    asm("mov.b64 %0, {%1, %1};" : "=l"(r) : "r"(u));
    return r;
}
__device__ __forceinline__ void fma2(ULL& d, ULL a, ULL b) {
    asm("fma.rn.f32x2 %0, %1, %2, %0;" : "+l"(d) : "l"(a), "l"(b));
}
__device__ __forceinline__ float f2lo(ULL a) { return __uint_as_float((unsigned)(a & 0xFFFFFFFFull)); }
__device__ __forceinline__ float f2hi(ULL a) { return __uint_as_float((unsigned)(a >> 32)); }

// ---------------- MLP layer 0+1: h1 = relu(relu(xm@w0+b0)@w1+b1) ----------------
__global__ void k_mlp01(const float* __restrict__ xm,
                        const float* __restrict__ w0, const float* __restrict__ b0,
                        const float* __restrict__ w1, const float* __restrict__ b1) {
    int b = blockIdx.x;          // 16 blocks
    int t = threadIdx.x;         // 256 threads
    __shared__ float sm[16];
    __shared__ float sh0[256];
    if (t < 16) sm[t] = xm[b * 16 + t];
    __syncthreads();
    // h0: 256 outputs, one per thread
    float a = b0[t];
    #pragma unroll
    for (int k = 0; k < 16; k++) a += sm[k] * w0[k * 256 + t];
    sh0[t] = fmaxf(a, 0.f);
    __syncthreads();
    // h1: 512 outputs, 2 per thread
    for (int j = t; j < 512; j += 256) {
        float a1 = b1[j];
        for (int k = 0; k < 256; k++) a1 += sh0[k] * w1[k * 512 + j];
        g_h1[b * 512 + j] = fmaxf(a1, 0.f);
    }
}

// ---------------- MLP layer 2: flat = relu(h1@w2+b2), all 16 samples per block ----------------
__global__ void k_mlp2(const float* __restrict__ w2, const float* __restrict__ b2) {
    __shared__ float sh1[16 * 512];
    int t = threadIdx.x;  // 256
    for (int i = t; i < 16 * 512; i += 256) sh1[i] = g_h1[i];
    __syncthreads();
    int j = blockIdx.x * 256 + t;
    if (j >= TOTAL_W) return;
    float acc[16];
    float bb = b2[j];
    #pragma unroll
    for (int s = 0; s < 16; s++) acc[s] = bb;
    for (int k = 0; k < 512; k++) {
        float w = w2[k * TOTAL_W + j];
        #pragma unroll
        for (int s = 0; s < 16; s++) acc[s] += sh1[s * 512 + k] * w;
    }
    #pragma unroll
    for (int s = 0; s < 16; s++) g_flat[s * TOTAL_W + j] = fmaxf(acc[s], 0.f);
}

// ---------------- conv0: 1 -> 32 channels ----------------
// grid (16 tx, 16 ty, 16 batch), block 256, each thread 1 pixel x 32 oc
__global__ void k_conv0(const float* __restrict__ x) {
    int b = blockIdx.z;
    int t = threadIdx.x;
    __shared__ float wsh[288];
    for (int i = t; i < 288; i += 256) wsh[i] = g_flat[b * TOTAL_W + i];
    __syncthreads();
    int px = blockIdx.x * 16 + (t & 15);
    int py = blockIdx.y * 16 + (t >> 4);
    float win[9];
    #pragma unroll
    for (int dy = 0; dy < 3; dy++)
        #pragma unroll
        for (int dx = 0; dx < 3; dx++) {
            int yy = py + dy - 1, xx = px + dx - 1;
            win[dy * 3 + dx] = (yy >= 0 && yy < H && xx >= 0 && xx < W)
                                   ? x[(b * H + yy) * W + xx] : 0.f;
        }
    #pragma unroll
    for (int oc = 0; oc < 32; oc++) {
        float a = 0.f;
        #pragma unroll
        for (int k = 0; k < 9; k++) a += win[k] * wsh[oc * 9 + k];
        g_c0[((b * 32 + oc) * H + py) * W + px] = a;
    }
}

// ---------------- conv1: 32 -> 64 channels (dominant: 19.3 GMAC) ----------------
// grid (16,16,16), block 256. Block tile: 16x16 spatial x 64 oc.
// Thread: 1x4 horizontal strip x 16 oc (as 8 fp32x2 oc-pairs). FFMA2 inner loop.
__global__ void __launch_bounds__(256, 2) k_conv1() {
    int b = blockIdx.z;
    int tx0 = blockIdx.x * 16, ty0 = blockIdx.y * 16;
    __shared__ float insh[8 * 18 * 21];   // 8 ic chunk, rows 18, stride 21 (pad)
    __shared__ float wsh[8 * 9 * 64];     // [(icl*9+k)*64 + oc], oc contiguous

    int t = threadIdx.x;
    int ocg = t >> 6;            // 0..3 -> oc group of 16
    int q = t & 63;
    int row = q >> 2;            // 0..15
    int sx = q & 3;              // 0..3
    int X = sx * 4;              // out x base within tile

    ULL acc[4][8];
    #pragma unroll
    for (int p = 0; p < 4; p++)
        #pragma unroll
        for (int u = 0; u < 8; u++) acc[p][u] = 0ull;

    const float* wbase = g_flat + b * TOTAL_W + OFF_W1;

    for (int cc = 0; cc < 4; cc++) {      // ic chunks of 8
        __syncthreads();
        // stage input tile: 8 ch x 18 x 18 (halo 1), zero-pad borders
        for (int i = t; i < 8 * 324; i += 256) {
            int icl = i / 324;
            int rem = i - icl * 324;
            int r = rem / 18, c = rem - r * 18;
            int y = ty0 + r - 1, xx = tx0 + c - 1;
            int ic = cc * 8 + icl;
            insh[icl * 378 + r * 21 + c] =
                (y >= 0 && y < H && xx >= 0 && xx < W)
                    ? g_c0[((b * 32 + ic) * H + y) * W + xx] : 0.f;
        }
        // stage weights transposed: wsh[(icl*9+k)*64 + oc] = w[oc][cc*8+icl][k]
        for (int i = t; i < 4608; i += 256) {
            int oc = i & 63;
            int rest = i >> 6;            // 0..71 = icl*9+k
            int icl = rest / 9, k = rest - icl * 9;
            wsh[i] = wbase[(oc * 32 + cc * 8 + icl) * 9 + k];
        }
        __syncthreads();

        for (int icl = 0; icl < 8; icl++) {
            const float* ibase = &insh[icl * 378 + row * 21 + X];
            #pragma unroll
            for (int dy = 0; dy < 3; dy++) {
                const float* rp = ibase + dy * 21;
                ULL p[6];
                #pragma unroll
                for (int j = 0; j < 6; j++) p[j] = pack2(rp[j]);
                #pragma unroll
                for (int dx = 0; dx < 3; dx++) {
                    const ulonglong2* wp =
                        (const ulonglong2*)&wsh[(icl * 9 + dy * 3 + dx) * 64 + ocg * 16];
                    ulonglong2 wa = wp[0], wb2 = wp[1], wc = wp[2], wd = wp[3];
                    ULL w[8] = {wa.x, wa.y, wb2.x, wb2.y, wc.x, wc.y, wd.x, wd.y};
                    #pragma unroll
                    for (int px = 0; px < 4; px++) {
                        ULL pv = p[px + dx];
                        #pragma unroll
                        for (int u = 0; u < 8; u++) fma2(acc[px][u], pv, w[u]);
                    }
                }
            }
        }
    }

    // store: per oc a float4 (4 consecutive x)
    int y = ty0 + row;
    int xb = tx0 + X;
    #pragma unroll
    for (int u = 0; u < 8; u++) {
        int oc0 = ocg * 16 + 2 * u;
        float4 vlo = make_float4(f2lo(acc[0][u]), f2lo(acc[1][u]), f2lo(acc[2][u]), f2lo(acc[3][u]));
        float4 vhi = make_float4(f2hi(acc[0][u]), f2hi(acc[1][u]), f2hi(acc[2][u]), f2hi(acc[3][u]));
        *(float4*)&g_c1[(((size_t)b * 64 + oc0) * H + y) * W + xb] = vlo;
        *(float4*)&g_c1[(((size_t)b * 64 + oc0 + 1) * H + y) * W + xb] = vhi;
    }
}

// ---------------- conv2: 64 -> 1 channel ----------------
// grid (16,16,16), block 256, thread = 1 pixel; ic chunks of 16 staged in smem
__global__ void k_conv2(float* __restrict__ out) {
    int b = blockIdx.z;
    int tx0 = blockIdx.x * 16, ty0 = blockIdx.y * 16;
    __shared__ float s2[16 * 18 * 19];    // 16 ic, rows 18, stride 19
    __shared__ float w2s[16 * 9];
    int t = threadIdx.x;
    int px = t & 15, py = t >> 4;
    const float* wb = g_flat + b * TOTAL_W + OFF_W2;   // [ic][3][3] since oc=1
    float acc = 0.f;

    for (int cc = 0; cc < 4; cc++) {
        __syncthreads();
        for (int i = t; i < 16 * 324; i += 256) {
            int icl = i / 324;
            int rem = i - icl * 324;
            int r = rem / 18, c = rem - r * 18;
            int y = ty0 + r - 1, xx = tx0 + c - 1;
            int ic = cc * 16 + icl;
            s2[icl * 342 + r * 19 + c] =
                (y >= 0 && y < H && xx >= 0 && xx < W)
                    ? g_c1[(((size_t)b * 64 + ic) * H + y) * W + xx] : 0.f;
        }
        for (int i = t; i < 144; i += 256)
            w2s[i] = wb[cc * 16 * 9 + i];
        __syncthreads();

        for (int icl = 0; icl < 16; icl++) {
            const float* sp = &s2[icl * 342 + py * 19 + px];
            const float* wp = &w2s[icl * 9];
            #pragma unroll
            for (int dy = 0; dy < 3; dy++)
                #pragma unroll
                for (int dx = 0; dx < 3; dx++)
                    acc += sp[dy * 19 + dx] * wp[dy * 3 + dx];
        }
    }
    out[(size_t)b * H * W + (ty0 + py) * W + (tx0 + px)] = acc;
}

// ---------------------------------------------------------------------------
extern "C" void kernel_launch(void* const* d_in, const int* in_sizes, int n_in,
                              void* d_out, int out_size) {
    const float* x_meta = (const float*)d_in[0];
    const float* x      = (const float*)d_in[1];
    const float* w0     = (const float*)d_in[2];
    const float* b0     = (const float*)d_in[3];
    const float* w1     = (const float*)d_in[4];
    const float* b1     = (const float*)d_in[5];
    const float* w2     = (const float*)d_in[6];
    const float* b2     = (const float*)d_in[7];
    float* out = (float*)d_out;

    k_mlp01<<<16, 256>>>(x_meta, w0, b0, w1, b1);
    k_mlp2<<<(TOTAL_W + 255) / 256, 256>>>(w2, b2);
    k_conv0<<<dim3(16, 16, 16), 256>>>(x);
    k_conv1<<<dim3(16, 16, 16), 256>>>();
    k_conv2<<<dim3(16, 16, 16), 256>>>(out);
}

// round 3
// speedup vs baseline: 1.4796x; 1.4796x over previous
#include <cuda_runtime.h>
#include <cuda_bf16.h>
#include <cstdint>

// ---------------------------------------------------------------------------
// DynamicModel hypernetwork:
//   MLP(16->256->512->19296, relu all) generates per-sample conv weights
//   conv0: 1->32 3x3 SAME ; conv1: 32->64 (mma.sync tf32) ; conv2: 64->1
//   B=16, H=W=256
// ---------------------------------------------------------------------------

static const int B = 16, H = 256, W = 256;
static const int TOTAL_W = 19296;
static const int OFF_W1 = 288;
static const int OFF_W2 = 18720;

// Weight layout for conv1 (per batch): row = (s*4+kk)*4 + jl, 144 rows,
// each row 68 float2 (oc 0..63 used, pad to 68): elem f2[oc] = (w[j=jl], w[j=jl+4])
static const int WROW_F2 = 68;
static const int WT_PER_B = 144 * WROW_F2 * 2;   // 19584 floats

// Scratch
__device__ float g_h1[16 * 512];
__device__ float g_flat[16 * TOTAL_W];
__device__ float g_wt[16 * WT_PER_B];
__device__ float g_c0[16 * 256 * 256 * 32];              // channel-last [b][y][x][ic]
__device__ float g_c1[(size_t)16 * 64 * 256 * 256];      // planar [b][oc][y][x]

// ---------------- helpers ----------------
__device__ __forceinline__ float tf32r(float x) {
    unsigned u;
    asm("cvt.rna.tf32.f32 %0, %1;" : "=r"(u) : "f"(x));
    return __uint_as_float(u);
}

__device__ __forceinline__ void mma_tf32(float d[4], const float2 a0, const float2 a1,
                                         const float2 bf) {
    // A regs: a0 = (col jl, col jl+4) at row m ; a1 = same at row m+8
    // order: {a0.x (r,c), a1.x (r+8,c), a0.y (r,c+4), a1.y (r+8,c+4)}
    asm volatile(
        "mma.sync.aligned.m16n8k8.row.col.f32.tf32.tf32.f32 "
        "{%0,%1,%2,%3}, {%4,%5,%6,%7}, {%8,%9}, {%0,%1,%2,%3};"
        : "+f"(d[0]), "+f"(d[1]), "+f"(d[2]), "+f"(d[3])
        : "r"(__float_as_uint(a0.x)), "r"(__float_as_uint(a1.x)),
          "r"(__float_as_uint(a0.y)), "r"(__float_as_uint(a1.y)),
          "r"(__float_as_uint(bf.x)), "r"(__float_as_uint(bf.y)));
}

// ---------------- MLP layer 0+1 ----------------
__global__ void k_mlp01(const float* __restrict__ xm,
                        const float* __restrict__ w0, const float* __restrict__ b0,
                        const float* __restrict__ w1, const float* __restrict__ b1) {
    int b = blockIdx.x;
    int t = threadIdx.x;
    __shared__ float sm[16];
    __shared__ float sh0[256];
    if (t < 16) sm[t] = xm[b * 16 + t];
    __syncthreads();
    float a = b0[t];
    #pragma unroll
    for (int k = 0; k < 16; k++) a += sm[k] * w0[k * 256 + t];
    sh0[t] = fmaxf(a, 0.f);
    __syncthreads();
    for (int j = t; j < 512; j += 256) {
        float a1 = b1[j];
        for (int k = 0; k < 256; k++) a1 += sh0[k] * w1[k * 512 + j];
        g_h1[b * 512 + j] = fmaxf(a1, 0.f);
    }
}

// ---------------- MLP layer 2 ----------------
__global__ void k_mlp2(const float* __restrict__ w2, const float* __restrict__ b2) {
    __shared__ float sh1[16 * 512];
    int t = threadIdx.x;
    for (int i = t; i < 16 * 512; i += 256) sh1[i] = g_h1[i];
    __syncthreads();
    int j = blockIdx.x * 256 + t;
    if (j >= TOTAL_W) return;
    float acc[16];
    float bb = b2[j];
    #pragma unroll
    for (int s = 0; s < 16; s++) acc[s] = bb;
    for (int k = 0; k < 512; k++) {
        float w = w2[k * TOTAL_W + j];
        #pragma unroll
        for (int s = 0; s < 16; s++) acc[s] += sh1[s * 512 + k] * w;
    }
    #pragma unroll
    for (int s = 0; s < 16; s++) g_flat[s * TOTAL_W + j] = fmaxf(acc[s], 0.f);
}

// ---------------- weight prep for conv1 mma (tf32-rounded, fragment layout) ----------------
__global__ void k_wprep() {
    int b = blockIdx.x, s = blockIdx.y;
    int t = threadIdx.x;
    const float* src = g_flat + b * TOTAL_W + OFF_W1;
    // i -> kk(4), jl(4), oc(64), jh(2)
    for (int i = t; i < 2048; i += 256) {
        int kk = i >> 9;
        int rem = i & 511;
        int jl = rem >> 7;
        int rem2 = rem & 127;
        int oc = rem2 >> 1, jh = rem2 & 1;
        g_wt[b * WT_PER_B + (((s * 4 + kk) * 4 + jl) * WROW_F2 + oc) * 2 + jh] =
            tf32r(src[(oc * 32 + kk * 8 + jh * 4 + jl) * 9 + s]);
    }
}

// ---------------- conv0: 1 -> 32, channel-last output, tf32-rounded ----------------
__global__ void k_conv0(const float* __restrict__ x) {
    int b = blockIdx.z;
    int t = threadIdx.x;
    __shared__ float wsh[288];
    for (int i = t; i < 288; i += 256) wsh[i] = g_flat[b * TOTAL_W + i];
    __syncthreads();
    int px = blockIdx.x * 16 + (t & 15);
    int py = blockIdx.y * 16 + (t >> 4);
    float win[9];
    #pragma unroll
    for (int dy = 0; dy < 3; dy++)
        #pragma unroll
        for (int dx = 0; dx < 3; dx++) {
            int yy = py + dy - 1, xx = px + dx - 1;
            win[dy * 3 + dx] = (yy >= 0 && yy < H && xx >= 0 && xx < W)
                                   ? x[(b * H + yy) * W + xx] : 0.f;
        }
    float* dst = g_c0 + ((size_t)((b * H + py) * W + px)) * 32;
    #pragma unroll
    for (int g4 = 0; g4 < 8; g4++) {
        float4 v;
        float* vp = &v.x;
        #pragma unroll
        for (int j = 0; j < 4; j++) {
            int oc = g4 * 4 + j;
            float a = 0.f;
            #pragma unroll
            for (int k = 0; k < 9; k++) a += win[k] * wsh[oc * 9 + k];
            vp[j] = tf32r(a);
        }
        *(float4*)(dst + g4 * 4) = v;
    }
}

// ---------------- conv1: tf32 mma.sync implicit GEMM ----------------
// Block: batch b, 4 output rows x 64 px (M=256), all 64 oc (N=64), K=288.
// 8 warps = 4 M-slices(64 px = 1 row) x 2 N-slices(32 oc).
// Input smem: float2 pairs (ic=kk*8+jl, +4), index ((kk*4+jl)*6 + r)*74 + u
// Weight smem: float2 pairs (j=jl, jl+4),  index ((s*4+kk)*4 + jl)*68 + oc
static const int SMW_BYTES = 144 * WROW_F2 * 8;          // 78336
static const int SMI_F2 = 16 * 6 * 74;                   // 7104 float2
static const int CONV1_SMEM = SMW_BYTES + SMI_F2 * 8;    // 135168

__global__ void __launch_bounds__(256) k_conv1mma() {
    extern __shared__ char smem[];
    float2* smw = (float2*)smem;
    float2* smi = (float2*)(smem + SMW_BYTES);

    int t = threadIdx.x;
    int b = blockIdx.z;
    int x0 = blockIdx.x * 64;
    int y0 = blockIdx.y * 4;

    // stage weights (straight copy, layout prebuilt by k_wprep)
    {
        const float4* src = (const float4*)(g_wt + (size_t)b * WT_PER_B);
        float4* dst = (float4*)smw;
        for (int i = t; i < WT_PER_B / 4; i += 256) dst[i] = src[i];
    }
    // stage input rows y0-1..y0+4, x0-1..x0+64, transposed to pair-interleaved planes
    for (int idx = t; idx < 6 * 66 * 8; idx += 256) {
        int c8 = idx & 7;
        int rest = idx >> 3;
        int u = rest % 66;
        int r = rest / 66;
        int gy = y0 - 1 + r, gx = x0 - 1 + u;
        float4 v = make_float4(0.f, 0.f, 0.f, 0.f);
        if ((unsigned)gy < 256u && (unsigned)gx < 256u)
            v = *(const float4*)(g_c0 + ((size_t)((b * 256 + gy) * 256 + gx)) * 32 + c8 * 4);
        int kk = c8 >> 1, h = c8 & 1;
        float* base = (float*)smi;
        const float* vp = &v.x;
        #pragma unroll
        for (int e = 0; e < 4; e++)
            base[(((kk * 4 + e) * 6 + r) * 74 + u) * 2 + h] = vp[e];
    }
    __syncthreads();

    int wid = t >> 5, lane = t & 31;
    int wm = wid & 3;            // M slice = output row
    int wn = wid >> 2;           // N slice
    int oc0 = wn * 32;
    int lrow = lane >> 2, lcol = lane & 3;

    float d[16][4];
    #pragma unroll
    for (int i = 0; i < 16; i++)
        #pragma unroll
        for (int j = 0; j < 4; j++) d[i][j] = 0.f;

    for (int s = 0; s < 9; s++) {
        int dy = s / 3;
        int dx = s - dy * 3;
        #pragma unroll
        for (int kk = 0; kk < 4; kk++) {
            // B fragments (weights): one LDS.64 each
            float2 bf[4];
            const float2* wrow = smw + ((s * 4 + kk) * 4 + lcol) * WROW_F2 + oc0 + lrow;
            #pragma unroll
            for (int ni = 0; ni < 4; ni++) bf[ni] = wrow[ni * 8];
            // A fragments (pixels)
            const float2* arow = smi + ((kk * 4 + lcol) * 6 + (wm + dy)) * 74 + lrow + dx;
            float2 af0[4], af1[4];
            #pragma unroll
            for (int mi = 0; mi < 4; mi++) {
                af0[mi] = arow[mi * 16];
                af1[mi] = arow[mi * 16 + 8];
            }
            #pragma unroll
            for (int mi = 0; mi < 4; mi++)
                #pragma unroll
                for (int ni = 0; ni < 4; ni++)
                    mma_tf32(d[mi * 4 + ni], af0[mi], af1[mi], bf[ni]);
        }
    }

    // store: planar g_c1[b][oc][y][x]
    int yo = y0 + wm;
    #pragma unroll
    for (int mi = 0; mi < 4; mi++) {
        int xb = x0 + mi * 16 + lrow;
        #pragma unroll
        for (int ni = 0; ni < 4; ni++) {
            int oc = oc0 + ni * 8 + lcol * 2;
            float* p = &g_c1[(((size_t)b * 64 + oc) * 256 + yo) * 256 + xb];
            p[0] = d[mi * 4 + ni][0];
            p[65536] = d[mi * 4 + ni][1];
            p[8] = d[mi * 4 + ni][2];
            p[65536 + 8] = d[mi * 4 + ni][3];
        }
    }
}

// ---------------- conv2: 64 -> 1 ----------------
__global__ void k_conv2(float* __restrict__ out) {
    int b = blockIdx.z;
    int tx0 = blockIdx.x * 16, ty0 = blockIdx.y * 16;
    __shared__ float s2[16 * 18 * 19];
    __shared__ float w2s[16 * 9];
    int t = threadIdx.x;
    int px = t & 15, py = t >> 4;
    const float* wb = g_flat + b * TOTAL_W + OFF_W2;
    float acc = 0.f;

    for (int cc = 0; cc < 4; cc++) {
        __syncthreads();
        for (int i = t; i < 16 * 324; i += 256) {
            int icl = i / 324;
            int rem = i - icl * 324;
            int r = rem / 18, c = rem - r * 18;
            int y = ty0 + r - 1, xx = tx0 + c - 1;
            int ic = cc * 16 + icl;
            s2[icl * 342 + r * 19 + c] =
                (y >= 0 && y < H && xx >= 0 && xx < W)
                    ? g_c1[(((size_t)b * 64 + ic) * H + y) * W + xx] : 0.f;
        }
        for (int i = t; i < 144; i += 256)
            w2s[i] = wb[cc * 16 * 9 + i];
        __syncthreads();

        for (int icl = 0; icl < 16; icl++) {
            const float* sp = &s2[icl * 342 + py * 19 + px];
            const float* wp = &w2s[icl * 9];
            #pragma unroll
            for (int dy = 0; dy < 3; dy++)
                #pragma unroll
                for (int dx = 0; dx < 3; dx++)
                    acc += sp[dy * 19 + dx] * wp[dy * 3 + dx];
        }
    }
    out[(size_t)b * H * W + (ty0 + py) * W + (tx0 + px)] = acc;
}

// ---------------------------------------------------------------------------
extern "C" void kernel_launch(void* const* d_in, const int* in_sizes, int n_in,
                              void* d_out, int out_size) {
    const float* x_meta = (const float*)d_in[0];
    const float* x      = (const float*)d_in[1];
    const float* w0     = (const float*)d_in[2];
    const float* b0     = (const float*)d_in[3];
    const float* w1     = (const float*)d_in[4];
    const float* b1     = (const float*)d_in[5];
    const float* w2     = (const float*)d_in[6];
    const float* b2     = (const float*)d_in[7];
    float* out = (float*)d_out;

    static int smem_set = 0;
    if (!smem_set) {
        cudaFuncSetAttribute(k_conv1mma, cudaFuncAttributeMaxDynamicSharedMemorySize,
                             CONV1_SMEM);
        smem_set = 1;
    }

    k_mlp01<<<16, 256>>>(x_meta, w0, b0, w1, b1);
    k_mlp2<<<(TOTAL_W + 255) / 256, 256>>>(w2, b2);
    k_wprep<<<dim3(16, 9), 256>>>();
    k_conv0<<<dim3(16, 16, 16), 256>>>(x);
    k_conv1mma<<<dim3(4, 64, 16), 256, CONV1_SMEM>>>();
    k_conv2<<<dim3(16, 16, 16), 256>>>(out);
}